// round 8
// baseline (speedup 1.0000x reference)
#include <cuda_runtime.h>
#include <math.h>
#include <stdint.h>

#define BB 4
#define NN 2048
#define DD 512
#define HH 8
#define DH 64
#define HD 512        // HH*DH
#define QKVC 1536     // 3*HH*DH
#define MAXREL 200

// ---- scratch (static device globals; no allocation allowed) ----
__device__ float g_xn[BB * NN * DD];        // LN output, tf32-rounded
__device__ float g_wqkv[DD * QKVC];         // tf32-rounded weights
__device__ float g_wout[HD * DD];
__device__ float g_q[BB * HH * NN * DH];    // [b,h,n,d]  tf32, pre-scaled
__device__ float g_k[BB * HH * NN * DH];    // [b,h,n,d]  tf32
__device__ float g_vT[BB * HH * DH * NN];   // [b,h,d,n]  tf32
__device__ float g_attn[BB * NN * HD];      // tf32-rounded
__device__ float g_bias[NN * NN];           // fused rel-pos bias + mask

__device__ __forceinline__ float to_tf32(float x) {
    float r;
    asm("cvt.rna.tf32.f32 %0, %1;" : "=f"(r) : "f"(x));
    return r;
}

__device__ __forceinline__ void cp16(uint32_t s, const void* g) {
    asm volatile("cp.async.ca.shared.global [%0], [%1], 16;" :: "r"(s), "l"(g));
}
#define CP_COMMIT()  asm volatile("cp.async.commit_group;")
#define CP_WAIT(N)   asm volatile("cp.async.wait_group %0;" :: "n"(N))

#define MMA_TF32(d, a0,a1,a2,a3, b0,b1)                                        \
    asm volatile("mma.sync.aligned.m16n8k8.row.col.f32.tf32.tf32.f32 "         \
        "{%0,%1,%2,%3},{%4,%5,%6,%7},{%8,%9},{%0,%1,%2,%3};"                   \
        : "+f"((d)[0]), "+f"((d)[1]), "+f"((d)[2]), "+f"((d)[3])               \
        : "r"(a0), "r"(a1), "r"(a2), "r"(a3), "r"(b0), "r"(b1))

// ================= prep: rna-round weights to tf32 =================
__global__ __launch_bounds__(256) void round_w_kernel(const float* __restrict__ Wqkv,
                                                      const float* __restrict__ Wout) {
    int i = blockIdx.x * blockDim.x + threadIdx.x;   // float4 index
    const int nq4 = DD * QKVC / 4;
    const int no4 = HD * DD / 4;
    if (i < nq4) {
        float4 v = ((const float4*)Wqkv)[i];
        ((float4*)g_wqkv)[i] = make_float4(to_tf32(v.x), to_tf32(v.y), to_tf32(v.z), to_tf32(v.w));
    } else if (i < nq4 + no4) {
        int j = i - nq4;
        float4 v = ((const float4*)Wout)[j];
        ((float4*)g_wout)[j] = make_float4(to_tf32(v.x), to_tf32(v.y), to_tf32(v.z), to_tf32(v.w));
    }
}

// ================= prep: fused bias = mask ? rel_table : -1e9 =================
__global__ __launch_bounds__(256) void bias_kernel(const float* __restrict__ rel_table,
                                                   const int* __restrict__ tmask) {
    int i = blockIdx.x * 256 + threadIdx.x;          // float4 index over NN*NN/4
    int r = i >> 9;                                  // (4i)/2048
    int c0 = (i << 2) & (NN - 1);
    int4 m = ((const int4*)tmask)[i];
    float4 o;
    int rel;
    rel = min(max(r - c0,     -(MAXREL - 1)), MAXREL - 1) + (MAXREL - 1);
    o.x = (m.x == 0) ? -1e9f : __ldg(&rel_table[rel]);
    rel = min(max(r - c0 - 1, -(MAXREL - 1)), MAXREL - 1) + (MAXREL - 1);
    o.y = (m.y == 0) ? -1e9f : __ldg(&rel_table[rel]);
    rel = min(max(r - c0 - 2, -(MAXREL - 1)), MAXREL - 1) + (MAXREL - 1);
    o.z = (m.z == 0) ? -1e9f : __ldg(&rel_table[rel]);
    rel = min(max(r - c0 - 3, -(MAXREL - 1)), MAXREL - 1) + (MAXREL - 1);
    o.w = (m.w == 0) ? -1e9f : __ldg(&rel_table[rel]);
    ((float4*)g_bias)[i] = o;
}

// ================= LayerNorm: one warp per row, writes tf32 xn =================
__global__ __launch_bounds__(256) void ln_kernel(const float* __restrict__ x,
                                                 const float* __restrict__ gamma,
                                                 const float* __restrict__ beta) {
    int warp = (blockIdx.x * blockDim.x + threadIdx.x) >> 5;
    int lane = threadIdx.x & 31;
    if (warp >= BB * NN) return;
    const float4* row = reinterpret_cast<const float4*>(x + (size_t)warp * DD);
    float4 v[4];
    float s = 0.f, ss = 0.f;
#pragma unroll
    for (int i = 0; i < 4; ++i) {
        v[i] = row[lane + i * 32];
        s  += v[i].x + v[i].y + v[i].z + v[i].w;
        ss += v[i].x * v[i].x + v[i].y * v[i].y + v[i].z * v[i].z + v[i].w * v[i].w;
    }
#pragma unroll
    for (int off = 16; off; off >>= 1) {
        s  += __shfl_xor_sync(0xffffffffu, s,  off);
        ss += __shfl_xor_sync(0xffffffffu, ss, off);
    }
    float mu = s * (1.0f / DD);
    float rs = rsqrtf(ss * (1.0f / DD) - mu * mu + 1e-5f);
    float4* dst = reinterpret_cast<float4*>(g_xn + (size_t)warp * DD);
#pragma unroll
    for (int i = 0; i < 4; ++i) {
        int c = lane + i * 32;
        float4 gm = ((const float4*)gamma)[c];
        float4 be = ((const float4*)beta)[c];
        float4 o;
        o.x = to_tf32((v[i].x - mu) * rs * gm.x + be.x);
        o.y = to_tf32((v[i].y - mu) * rs * gm.y + be.y);
        o.z = to_tf32((v[i].z - mu) * rs * gm.z + be.z);
        o.w = to_tf32((v[i].w - mu) * rs * gm.w + be.w);
        dst[c] = o;
    }
}

// ========== shared tf32 GEMM skeleton: 128x128x16, 8 warps (4m x 2n), 32x64 warp tile ==========
#define GA(buf, r, c)  ((buf) * 2560 + (r) * 20 + (c))
#define GB(buf, r, c)  (5120 + (buf) * 2176 + (r) * 136 + (c))

#define GEMM_LOADA(buf, Ap, lda, k0)                                           \
    {                                                                          \
        _Pragma("unroll")                                                      \
        for (int i = 0; i < 2; ++i) {                                          \
            int idx = tid + i * 256;                                           \
            int r = idx >> 2, c = (idx & 3) * 4;                               \
            cp16(smb + GA(buf, r, c) * 4, (Ap) + (size_t)(m0 + r) * (lda) + (k0) + c); \
        }                                                                      \
    }
#define GEMM_LOADB(buf, Bp, ldb, k0)                                           \
    {                                                                          \
        _Pragma("unroll")                                                      \
        for (int i = 0; i < 2; ++i) {                                          \
            int idx = tid + i * 256;                                           \
            int r = idx >> 5, c = (idx & 31) * 4;                              \
            cp16(smb + GB(buf, r, c) * 4, (Bp) + (size_t)((k0) + r) * (ldb) + n0 + c); \
        }                                                                      \
    }

#define GEMM_MAIN(Ap, lda, Bp, ldb, KDIM)                                      \
    float acc[2][8][4] = {};                                                   \
    GEMM_LOADA(0, Ap, lda, 0);                                                 \
    GEMM_LOADB(0, Bp, ldb, 0);                                                 \
    CP_COMMIT();                                                               \
    for (int k0 = 0; k0 < (KDIM); k0 += 16) {                                  \
        int buf = (k0 >> 4) & 1;                                               \
        if (k0 > 0) __syncthreads();                                           \
        if (k0 + 16 < (KDIM)) {                                                \
            GEMM_LOADA(buf ^ 1, Ap, lda, k0 + 16);                             \
            GEMM_LOADB(buf ^ 1, Bp, ldb, k0 + 16);                             \
            CP_COMMIT();                                                       \
            CP_WAIT(1);                                                        \
        } else {                                                               \
            CP_WAIT(0);                                                        \
        }                                                                      \
        __syncthreads();                                                       \
        _Pragma("unroll")                                                      \
        for (int ks = 0; ks < 2; ++ks) {                                       \
            uint32_t af[2][4];                                                 \
            _Pragma("unroll")                                                  \
            for (int mi = 0; mi < 2; ++mi) {                                   \
                int r = wm + mi * 16 + g;                                      \
                af[mi][0] = __float_as_uint(sm[GA(buf, r,     ks * 8 + tig)]); \
                af[mi][1] = __float_as_uint(sm[GA(buf, r + 8, ks * 8 + tig)]); \
                af[mi][2] = __float_as_uint(sm[GA(buf, r,     ks * 8 + tig + 4)]); \
                af[mi][3] = __float_as_uint(sm[GA(buf, r + 8, ks * 8 + tig + 4)]); \
            }                                                                  \
            _Pragma("unroll")                                                  \
            for (int ni = 0; ni < 8; ++ni) {                                   \
                int cb = wn + ni * 8 + g;                                      \
                uint32_t b0 = __float_as_uint(sm[GB(buf, ks * 8 + tig,     cb)]); \
                uint32_t b1 = __float_as_uint(sm[GB(buf, ks * 8 + tig + 4, cb)]); \
                MMA_TF32(acc[0][ni], af[0][0], af[0][1], af[0][2], af[0][3], b0, b1); \
                MMA_TF32(acc[1][ni], af[1][0], af[1][1], af[1][2], af[1][3], b0, b1); \
            }                                                                  \
        }                                                                      \
    }

// ================= QKV GEMM (tf32 MMA): xn[8192,512] x Wqkv[512,1536] =================
__global__ __launch_bounds__(256, 2) void qkv_mma_kernel() {
    __shared__ float sm[9472];
    uint32_t smb = (uint32_t)__cvta_generic_to_shared(sm);
    int tid = threadIdx.x;
    int lane = tid & 31, wid = tid >> 5;
    int g = lane >> 2, tig = lane & 3;
    int wm = (wid >> 1) * 32, wn = (wid & 1) * 64;
    int m0 = blockIdx.y * 128, n0 = blockIdx.x * 128;

    GEMM_MAIN(g_xn, DD, g_wqkv, QKVC, DD);

#pragma unroll
    for (int ni = 0; ni < 8; ++ni) {
        int c = n0 + wn + ni * 8 + 2 * tig;
        int part = c >> 9, w = c & 511;
        int h = w >> 6, dd = w & 63;
#pragma unroll
        for (int mi = 0; mi < 2; ++mi) {
#pragma unroll
            for (int half = 0; half < 2; ++half) {
                int r = m0 + wm + mi * 16 + g + half * 8;
                int b = r >> 11, n = r & (NN - 1);
                size_t bh = (size_t)(b * HH + h);
                float v0 = acc[mi][ni][half * 2 + 0];
                float v1 = acc[mi][ni][half * 2 + 1];
                if (part == 0) {
                    *(float2*)&g_q[(bh * NN + n) * DH + dd] =
                        make_float2(to_tf32(v0 * 0.125f), to_tf32(v1 * 0.125f));
                } else if (part == 1) {
                    *(float2*)&g_k[(bh * NN + n) * DH + dd] =
                        make_float2(to_tf32(v0), to_tf32(v1));
                } else {
                    g_vT[(bh * DH + dd) * NN + n]     = to_tf32(v0);
                    g_vT[(bh * DH + dd + 1) * NN + n] = to_tf32(v1);
                }
            }
        }
    }
}

// ================= Out GEMM (tf32 MMA): attn[8192,512] x Wout[512,512] + bias =================
__global__ __launch_bounds__(256, 2) void out_mma_kernel(const float* __restrict__ bout,
                                                         float* __restrict__ out) {
    __shared__ float sm[9472];
    uint32_t smb = (uint32_t)__cvta_generic_to_shared(sm);
    int tid = threadIdx.x;
    int lane = tid & 31, wid = tid >> 5;
    int g = lane >> 2, tig = lane & 3;
    int wm = (wid >> 1) * 32, wn = (wid & 1) * 64;
    int m0 = blockIdx.y * 128, n0 = blockIdx.x * 128;

    GEMM_MAIN(g_attn, HD, g_wout, DD, HD);

#pragma unroll
    for (int ni = 0; ni < 8; ++ni) {
        int c = n0 + wn + ni * 8 + 2 * tig;
        float2 bo = *(const float2*)&bout[c];
#pragma unroll
        for (int mi = 0; mi < 2; ++mi) {
#pragma unroll
            for (int half = 0; half < 2; ++half) {
                int r = m0 + wm + mi * 16 + g + half * 8;
                *(float2*)&out[(size_t)r * DD + c] =
                    make_float2(acc[mi][ni][half * 2 + 0] + bo.x,
                                acc[mi][ni][half * 2 + 1] + bo.y);
            }
        }
    }
}

// ================= Flash attention, 512 threads / 16 warps =================
// warp (wm 0..7, wn 0..1): S = 16 rows x 32 keys; PV = 16 rows x 32 d-cols
// smem floats: QS[128][68], KS/VS double-buffered [64][68], PS[128][68], RED[2][128]
#define FS_QS   0
#define FS_KS   8704
#define FS_VS   13056
#define FS_STG  8704
#define FS_PS   26112
#define FS_RED  34816
#define FS_TOT  35072
#define FLASH_SMEM (FS_TOT * 4)
#define NT_TILES (NN / 64)

__global__ __launch_bounds__(512, 1) void flash_mma_kernel() {
    extern __shared__ float sm[];
    uint32_t smb = (uint32_t)__cvta_generic_to_shared(sm);

    int tid  = threadIdx.x;
    int lane = tid & 31, wid = tid >> 5;   // wid 0..15
    int g   = lane >> 2;
    int tig = lane & 3;
    int wm  = wid >> 1;                    // 0..7  (16 q-rows each)
    int wn  = wid & 1;                     // 0..1  (key/d half)
    int bh = blockIdx.y;
    int q0 = blockIdx.x * 128;
    const float* Q  = g_q  + (size_t)bh * NN * DH;
    const float* K  = g_k  + (size_t)bh * NN * DH;
    const float* Vt = g_vT + (size_t)bh * DH * NN;

    int lr = tid >> 4;            // 0..31
    int lc = (tid & 15) * 4;      // 0..60

    // Q tile 128x64 + first K/V tiles via cp.async
#pragma unroll
    for (int i = 0; i < 4; ++i) {
        int r = lr + i * 32;
        cp16(smb + (FS_QS + r * 68 + lc) * 4, Q + (size_t)(q0 + r) * DH + lc);
    }
#pragma unroll
    for (int i = 0; i < 2; ++i) {
        int r = lr + i * 32;
        cp16(smb + (FS_KS + r * 68 + lc) * 4, K + (size_t)r * DH + lc);
        cp16(smb + (FS_VS + r * 68 + lc) * 4, Vt + (size_t)r * NN + lc);
    }
    CP_COMMIT();

    float oa[4][4] = {};
    float mi[2] = {-INFINITY, -INFINITY};
    float li[2] = {0.f, 0.f};              // warp-partial (this wn's 32 keys)

    const int m_row = wm * 16 + g;
    const float* qb = sm + FS_QS + m_row * 68 + tig;

    for (int t = 0; t < NT_TILES; ++t) {
        int cur = t & 1;
        int k0 = t * 64;
        if (t > 0) __syncthreads();        // prev PV done reading buffer we overwrite
        if (t + 1 < NT_TILES) {
            int nxt = cur ^ 1;
#pragma unroll
            for (int i = 0; i < 2; ++i) {
                int r = lr + i * 32;
                cp16(smb + (FS_KS + nxt * FS_STG + r * 68 + lc) * 4,
                     K + (size_t)(k0 + 64 + r) * DH + lc);
                cp16(smb + (FS_VS + nxt * FS_STG + r * 68 + lc) * 4,
                     Vt + (size_t)r * NN + k0 + 64 + lc);
            }
            CP_COMMIT();
            CP_WAIT(1);
        } else {
            CP_WAIT(0);
        }
        __syncthreads();                   // tile t visible

        const float* kb = sm + FS_KS + cur * FS_STG + (wn * 32 + g) * 68 + tig;
        const float* vb = sm + FS_VS + cur * FS_STG + (wn * 32 + g) * 68 + tig;

        // ---- S = Q K^T over this warp's 32-key half: 8 ks x 4 nt ----
        float sa[4][4] = {};
#pragma unroll
        for (int ks = 0; ks < 8; ++ks) {
            uint32_t a0 = __float_as_uint(qb[ks * 8]);
            uint32_t a1 = __float_as_uint(qb[8 * 68 + ks * 8]);
            uint32_t a2 = __float_as_uint(qb[ks * 8 + 4]);
            uint32_t a3 = __float_as_uint(qb[8 * 68 + ks * 8 + 4]);
#pragma unroll
            for (int nt = 0; nt < 4; ++nt) {
                uint32_t b0 = __float_as_uint(kb[nt * 8 * 68 + ks * 8]);
                uint32_t b1 = __float_as_uint(kb[nt * 8 * 68 + ks * 8 + 4]);
                MMA_TF32(sa[nt], a0, a1, a2, a3, b0, b1);
            }
        }

        // ---- fused bias + local max ----
        float mloc[2];
#pragma unroll
        for (int ri = 0; ri < 2; ++ri) {
            int rl = m_row + ri * 8;
            int rg = q0 + rl;
            const float2* bp = (const float2*)(g_bias + (size_t)rg * NN + k0 + wn * 32);
            float mx = -INFINITY;
#pragma unroll
            for (int nt = 0; nt < 4; ++nt) {
                float2 bb = bp[nt * 4 + tig];
                float v0 = sa[nt][ri * 2 + 0] + bb.x;
                float v1 = sa[nt][ri * 2 + 1] + bb.y;
                sa[nt][ri * 2 + 0] = v0;
                sa[nt][ri * 2 + 1] = v1;
                mx = fmaxf(mx, fmaxf(v0, v1));
            }
            mx = fmaxf(mx, __shfl_xor_sync(0xffffffffu, mx, 1));
            mx = fmaxf(mx, __shfl_xor_sync(0xffffffffu, mx, 2));
            mloc[ri] = mx;
        }
        if (tig == 0) {
            sm[FS_RED + wn * 128 + m_row]     = mloc[0];
            sm[FS_RED + wn * 128 + m_row + 8] = mloc[1];
        }
        __syncthreads();                   // partner max visible

        // ---- online softmax with shared mnew; li stays warp-partial ----
#pragma unroll
        for (int ri = 0; ri < 2; ++ri) {
            int rl = m_row + ri * 8;
            float mOther = sm[FS_RED + (wn ^ 1) * 128 + rl];
            float mnew = fmaxf(mi[ri], fmaxf(mloc[ri], mOther));
            float f = __expf(mi[ri] - mnew);
            float sum = 0.f;
            float2* psr = (float2*)(sm + FS_PS + rl * 68 + wn * 32 + 2 * tig);
#pragma unroll
            for (int nt = 0; nt < 4; ++nt) {
                float e0 = to_tf32(__expf(sa[nt][ri * 2 + 0] - mnew));
                float e1 = to_tf32(__expf(sa[nt][ri * 2 + 1] - mnew));
                sum += e0 + e1;
                psr[nt * 4] = make_float2(e0, e1);
            }
            sum += __shfl_xor_sync(0xffffffffu, sum, 1);
            sum += __shfl_xor_sync(0xffffffffu, sum, 2);
            li[ri] = li[ri] * f + sum;
            mi[ri] = mnew;
#pragma unroll
            for (int nt = 0; nt < 4; ++nt) {
                oa[nt][ri * 2 + 0] *= f;
                oa[nt][ri * 2 + 1] *= f;
            }
        }
        __syncthreads();                   // full P rows (both partners) visible

        // ---- O += P V over this warp's 32 d-cols: full 64-key range ----
        const float* pb = sm + FS_PS + m_row * 68 + tig;
#pragma unroll
        for (int ks = 0; ks < 8; ++ks) {
            uint32_t a0 = __float_as_uint(pb[ks * 8]);
            uint32_t a1 = __float_as_uint(pb[8 * 68 + ks * 8]);
            uint32_t a2 = __float_as_uint(pb[ks * 8 + 4]);
            uint32_t a3 = __float_as_uint(pb[8 * 68 + ks * 8 + 4]);
#pragma unroll
            for (int nt = 0; nt < 4; ++nt) {
                uint32_t b0 = __float_as_uint(vb[nt * 8 * 68 + ks * 8]);
                uint32_t b1 = __float_as_uint(vb[nt * 8 * 68 + ks * 8 + 4]);
                MMA_TF32(oa[nt], a0, a1, a2, a3, b0, b1);
            }
        }
    }

    // ---- reduce li across wn partners (linear given shared rescales) ----
    __syncthreads();
    if (tig == 0) {
        sm[FS_RED + wn * 128 + m_row]     = li[0];
        sm[FS_RED + wn * 128 + m_row + 8] = li[1];
    }
    __syncthreads();
    float l0 = li[0] + sm[FS_RED + (wn ^ 1) * 128 + m_row];
    float l1 = li[1] + sm[FS_RED + (wn ^ 1) * 128 + m_row + 8];

    // ---- finalize: write [B, N, H*d] ----
    int b = bh >> 3, h = bh & 7;
    float inv0 = 1.0f / l0, inv1 = 1.0f / l1;
#pragma unroll
    for (int nt = 0; nt < 4; ++nt) {
        int col = h * DH + wn * 32 + nt * 8 + 2 * tig;
        int r0 = q0 + m_row;
        *(float2*)&g_attn[((size_t)(b * NN + r0)) * HD + col] =
            make_float2(to_tf32(oa[nt][0] * inv0), to_tf32(oa[nt][1] * inv0));
        *(float2*)&g_attn[((size_t)(b * NN + r0 + 8)) * HD + col] =
            make_float2(to_tf32(oa[nt][2] * inv1), to_tf32(oa[nt][3] * inv1));
    }
}

extern "C" void kernel_launch(void* const* d_in, const int* in_sizes, int n_in,
                              void* d_out, int out_size) {
    const float* x     = (const float*)d_in[0];
    const float* gamma = (const float*)d_in[1];
    const float* beta  = (const float*)d_in[2];
    const float* Wqkv  = (const float*)d_in[3];
    const float* Wout  = (const float*)d_in[4];
    const float* bout  = (const float*)d_in[5];
    const float* rel   = (const float*)d_in[6];
    const int*   tmask = (const int*)d_in[7];
    float* out = (float*)d_out;

    round_w_kernel<<<(DD * QKVC / 4 + HD * DD / 4 + 255) / 256, 256>>>(Wqkv, Wout);
    bias_kernel<<<NN * NN / 4 / 256, 256>>>(rel, tmask);
    ln_kernel<<<(BB * NN) / 8, 256>>>(x, gamma, beta);
    qkv_mma_kernel<<<dim3(QKVC / 128, (BB * NN) / 128), 256>>>();

    cudaFuncSetAttribute(flash_mma_kernel, cudaFuncAttributeMaxDynamicSharedMemorySize, FLASH_SMEM);
    flash_mma_kernel<<<dim3(NN / 128, BB * HH), 512, FLASH_SMEM>>>();

    out_mma_kernel<<<dim3(DD / 128, (BB * NN) / 128), 256>>>(bout, out);
}

// round 9
// speedup vs baseline: 1.1595x; 1.1595x over previous
#include <cuda_runtime.h>
#include <math.h>
#include <stdint.h>

#define BB 4
#define NN 2048
#define DD 512
#define HH 8
#define DH 64
#define HD 512        // HH*DH
#define QKVC 1536     // 3*HH*DH
#define MAXREL 200

// ---- scratch (static device globals; no allocation allowed) ----
__device__ float g_xn[BB * NN * DD];        // LN output, tf32-rounded
__device__ float g_wqkv[DD * QKVC];         // tf32-rounded weights
__device__ float g_wout[HD * DD];
__device__ float g_q[BB * HH * NN * DH];    // [b,h,n,d]  tf32, pre-scaled
__device__ float g_k[BB * HH * NN * DH];    // [b,h,n,d]  tf32
__device__ float g_vT[BB * HH * DH * NN];   // [b,h,d,n]  tf32
__device__ float g_attn[BB * NN * HD];      // tf32-rounded
__device__ float g_bias[NN * NN];           // fused rel-pos bias + mask

__device__ __forceinline__ float to_tf32(float x) {
    float r;
    asm("cvt.rna.tf32.f32 %0, %1;" : "=f"(r) : "f"(x));
    return r;
}

__device__ __forceinline__ void cp16(uint32_t s, const void* g) {
    asm volatile("cp.async.ca.shared.global [%0], [%1], 16;" :: "r"(s), "l"(g));
}
#define CP_COMMIT()  asm volatile("cp.async.commit_group;")
#define CP_WAIT(N)   asm volatile("cp.async.wait_group %0;" :: "n"(N))

#define MMA_TF32(d, a0,a1,a2,a3, b0,b1)                                        \
    asm volatile("mma.sync.aligned.m16n8k8.row.col.f32.tf32.tf32.f32 "         \
        "{%0,%1,%2,%3},{%4,%5,%6,%7},{%8,%9},{%0,%1,%2,%3};"                   \
        : "+f"((d)[0]), "+f"((d)[1]), "+f"((d)[2]), "+f"((d)[3])               \
        : "r"(a0), "r"(a1), "r"(a2), "r"(a3), "r"(b0), "r"(b1))

// one x4 ldmatrix: 4 m8n8 b16 units == 4 blocks of 8 rows x 4 u32
__device__ __forceinline__ void ldsm4(uint32_t& r0, uint32_t& r1, uint32_t& r2, uint32_t& r3,
                                      uint32_t a) {
    asm volatile("ldmatrix.sync.aligned.m8n8.x4.shared.b16 {%0,%1,%2,%3}, [%4];"
        : "=r"(r0), "=r"(r1), "=r"(r2), "=r"(r3) : "r"(a));
}

// ================= prep: rna-round weights to tf32 =================
__global__ __launch_bounds__(256) void round_w_kernel(const float* __restrict__ Wqkv,
                                                      const float* __restrict__ Wout) {
    int i = blockIdx.x * blockDim.x + threadIdx.x;   // float4 index
    const int nq4 = DD * QKVC / 4;
    const int no4 = HD * DD / 4;
    if (i < nq4) {
        float4 v = ((const float4*)Wqkv)[i];
        ((float4*)g_wqkv)[i] = make_float4(to_tf32(v.x), to_tf32(v.y), to_tf32(v.z), to_tf32(v.w));
    } else if (i < nq4 + no4) {
        int j = i - nq4;
        float4 v = ((const float4*)Wout)[j];
        ((float4*)g_wout)[j] = make_float4(to_tf32(v.x), to_tf32(v.y), to_tf32(v.z), to_tf32(v.w));
    }
}

// ================= prep: fused bias = mask ? rel_table : -1e9 =================
__global__ __launch_bounds__(256) void bias_kernel(const float* __restrict__ rel_table,
                                                   const int* __restrict__ tmask) {
    int i = blockIdx.x * 256 + threadIdx.x;          // float4 index over NN*NN/4
    int r = i >> 9;
    int c0 = (i << 2) & (NN - 1);
    int4 m = ((const int4*)tmask)[i];
    float4 o;
    int rel;
    rel = min(max(r - c0,     -(MAXREL - 1)), MAXREL - 1) + (MAXREL - 1);
    o.x = (m.x == 0) ? -1e9f : __ldg(&rel_table[rel]);
    rel = min(max(r - c0 - 1, -(MAXREL - 1)), MAXREL - 1) + (MAXREL - 1);
    o.y = (m.y == 0) ? -1e9f : __ldg(&rel_table[rel]);
    rel = min(max(r - c0 - 2, -(MAXREL - 1)), MAXREL - 1) + (MAXREL - 1);
    o.z = (m.z == 0) ? -1e9f : __ldg(&rel_table[rel]);
    rel = min(max(r - c0 - 3, -(MAXREL - 1)), MAXREL - 1) + (MAXREL - 1);
    o.w = (m.w == 0) ? -1e9f : __ldg(&rel_table[rel]);
    ((float4*)g_bias)[i] = o;
}

// ================= LayerNorm: one warp per row, writes tf32 xn =================
__global__ __launch_bounds__(256) void ln_kernel(const float* __restrict__ x,
                                                 const float* __restrict__ gamma,
                                                 const float* __restrict__ beta) {
    int warp = (blockIdx.x * blockDim.x + threadIdx.x) >> 5;
    int lane = threadIdx.x & 31;
    if (warp >= BB * NN) return;
    const float4* row = reinterpret_cast<const float4*>(x + (size_t)warp * DD);
    float4 v[4];
    float s = 0.f, ss = 0.f;
#pragma unroll
    for (int i = 0; i < 4; ++i) {
        v[i] = row[lane + i * 32];
        s  += v[i].x + v[i].y + v[i].z + v[i].w;
        ss += v[i].x * v[i].x + v[i].y * v[i].y + v[i].z * v[i].z + v[i].w * v[i].w;
    }
#pragma unroll
    for (int off = 16; off; off >>= 1) {
        s  += __shfl_xor_sync(0xffffffffu, s,  off);
        ss += __shfl_xor_sync(0xffffffffu, ss, off);
    }
    float mu = s * (1.0f / DD);
    float rs = rsqrtf(ss * (1.0f / DD) - mu * mu + 1e-5f);
    float4* dst = reinterpret_cast<float4*>(g_xn + (size_t)warp * DD);
#pragma unroll
    for (int i = 0; i < 4; ++i) {
        int c = lane + i * 32;
        float4 gm = ((const float4*)gamma)[c];
        float4 be = ((const float4*)beta)[c];
        float4 o;
        o.x = to_tf32((v[i].x - mu) * rs * gm.x + be.x);
        o.y = to_tf32((v[i].y - mu) * rs * gm.y + be.y);
        o.z = to_tf32((v[i].z - mu) * rs * gm.z + be.z);
        o.w = to_tf32((v[i].w - mu) * rs * gm.w + be.w);
        dst[c] = o;
    }
}

// ========== shared tf32 GEMM skeleton: 128x128x16, 8 warps (4m x 2n), 32x64 warp tile ==========
#define GA(buf, r, c)  ((buf) * 2560 + (r) * 20 + (c))
#define GB(buf, r, c)  (5120 + (buf) * 2176 + (r) * 136 + (c))

#define GEMM_LOADA(buf, Ap, lda, k0)                                           \
    {                                                                          \
        _Pragma("unroll")                                                      \
        for (int i = 0; i < 2; ++i) {                                          \
            int idx = tid + i * 256;                                           \
            int r = idx >> 2, c = (idx & 3) * 4;                               \
            cp16(smb + GA(buf, r, c) * 4, (Ap) + (size_t)(m0 + r) * (lda) + (k0) + c); \
        }                                                                      \
    }
#define GEMM_LOADB(buf, Bp, ldb, k0)                                           \
    {                                                                          \
        _Pragma("unroll")                                                      \
        for (int i = 0; i < 2; ++i) {                                          \
            int idx = tid + i * 256;                                           \
            int r = idx >> 5, c = (idx & 31) * 4;                              \
            cp16(smb + GB(buf, r, c) * 4, (Bp) + (size_t)((k0) + r) * (ldb) + n0 + c); \
        }                                                                      \
    }

#define GEMM_MAIN(Ap, lda, Bp, ldb, KDIM)                                      \
    float acc[2][8][4] = {};                                                   \
    GEMM_LOADA(0, Ap, lda, 0);                                                 \
    GEMM_LOADB(0, Bp, ldb, 0);                                                 \
    CP_COMMIT();                                                               \
    for (int k0 = 0; k0 < (KDIM); k0 += 16) {                                  \
        int buf = (k0 >> 4) & 1;                                               \
        if (k0 > 0) __syncthreads();                                           \
        if (k0 + 16 < (KDIM)) {                                                \
            GEMM_LOADA(buf ^ 1, Ap, lda, k0 + 16);                             \
            GEMM_LOADB(buf ^ 1, Bp, ldb, k0 + 16);                             \
            CP_COMMIT();                                                       \
            CP_WAIT(1);                                                        \
        } else {                                                               \
            CP_WAIT(0);                                                        \
        }                                                                      \
        __syncthreads();                                                       \
        _Pragma("unroll")                                                      \
        for (int ks = 0; ks < 2; ++ks) {                                       \
            uint32_t af[2][4];                                                 \
            _Pragma("unroll")                                                  \
            for (int mi = 0; mi < 2; ++mi) {                                   \
                int r = wm + mi * 16 + g;                                      \
                af[mi][0] = __float_as_uint(sm[GA(buf, r,     ks * 8 + tig)]); \
                af[mi][1] = __float_as_uint(sm[GA(buf, r + 8, ks * 8 + tig)]); \
                af[mi][2] = __float_as_uint(sm[GA(buf, r,     ks * 8 + tig + 4)]); \
                af[mi][3] = __float_as_uint(sm[GA(buf, r + 8, ks * 8 + tig + 4)]); \
            }                                                                  \
            _Pragma("unroll")                                                  \
            for (int ni = 0; ni < 8; ++ni) {                                   \
                int cb = wn + ni * 8 + g;                                      \
                uint32_t b0 = __float_as_uint(sm[GB(buf, ks * 8 + tig,     cb)]); \
                uint32_t b1 = __float_as_uint(sm[GB(buf, ks * 8 + tig + 4, cb)]); \
                MMA_TF32(acc[0][ni], af[0][0], af[0][1], af[0][2], af[0][3], b0, b1); \
                MMA_TF32(acc[1][ni], af[1][0], af[1][1], af[1][2], af[1][3], b0, b1); \
            }                                                                  \
        }                                                                      \
    }

// ================= QKV GEMM (tf32 MMA): xn[8192,512] x Wqkv[512,1536] =================
__global__ __launch_bounds__(256, 2) void qkv_mma_kernel() {
    __shared__ float sm[9472];
    uint32_t smb = (uint32_t)__cvta_generic_to_shared(sm);
    int tid = threadIdx.x;
    int lane = tid & 31, wid = tid >> 5;
    int g = lane >> 2, tig = lane & 3;
    int wm = (wid >> 1) * 32, wn = (wid & 1) * 64;
    int m0 = blockIdx.y * 128, n0 = blockIdx.x * 128;

    GEMM_MAIN(g_xn, DD, g_wqkv, QKVC, DD);

#pragma unroll
    for (int ni = 0; ni < 8; ++ni) {
        int c = n0 + wn + ni * 8 + 2 * tig;
        int part = c >> 9, w = c & 511;
        int h = w >> 6, dd = w & 63;
#pragma unroll
        for (int mi = 0; mi < 2; ++mi) {
#pragma unroll
            for (int half = 0; half < 2; ++half) {
                int r = m0 + wm + mi * 16 + g + half * 8;
                int b = r >> 11, n = r & (NN - 1);
                size_t bh = (size_t)(b * HH + h);
                float v0 = acc[mi][ni][half * 2 + 0];
                float v1 = acc[mi][ni][half * 2 + 1];
                if (part == 0) {
                    *(float2*)&g_q[(bh * NN + n) * DH + dd] =
                        make_float2(to_tf32(v0 * 0.125f), to_tf32(v1 * 0.125f));
                } else if (part == 1) {
                    *(float2*)&g_k[(bh * NN + n) * DH + dd] =
                        make_float2(to_tf32(v0), to_tf32(v1));
                } else {
                    g_vT[(bh * DH + dd) * NN + n]     = to_tf32(v0);
                    g_vT[(bh * DH + dd + 1) * NN + n] = to_tf32(v1);
                }
            }
        }
    }
}

// ================= Out GEMM (tf32 MMA): attn[8192,512] x Wout[512,512] + bias =================
__global__ __launch_bounds__(256, 2) void out_mma_kernel(const float* __restrict__ bout,
                                                         float* __restrict__ out) {
    __shared__ float sm[9472];
    uint32_t smb = (uint32_t)__cvta_generic_to_shared(sm);
    int tid = threadIdx.x;
    int lane = tid & 31, wid = tid >> 5;
    int g = lane >> 2, tig = lane & 3;
    int wm = (wid >> 1) * 32, wn = (wid & 1) * 64;
    int m0 = blockIdx.y * 128, n0 = blockIdx.x * 128;

    GEMM_MAIN(g_attn, HD, g_wout, DD, HD);

#pragma unroll
    for (int ni = 0; ni < 8; ++ni) {
        int c = n0 + wn + ni * 8 + 2 * tig;
        float2 bo = *(const float2*)&bout[c];
#pragma unroll
        for (int mi = 0; mi < 2; ++mi) {
#pragma unroll
            for (int half = 0; half < 2; ++half) {
                int r = m0 + wm + mi * 16 + g + half * 8;
                *(float2*)&out[(size_t)r * DD + c] =
                    make_float2(acc[mi][ni][half * 2 + 0] + bo.x,
                                acc[mi][ni][half * 2 + 1] + bo.y);
            }
        }
    }
}

// ================= Flash attention: 8 warps, ldmatrix fragment loads =================
// smem floats (stride 68): QS[128][68], KS[2][64][68] d-cols, VS[2][64][68] (rows=d, cols=key),
// PS[128][68]
#define FS_QS   0
#define FS_KS   8704
#define FS_VS   13056
#define FS_STG  8704
#define FS_PS   26112
#define FS_TOT  34816
#define FLASH_SMEM (FS_TOT * 4)
#define NT_TILES (NN / 64)

__global__ __launch_bounds__(256, 1) void flash_mma_kernel() {
    extern __shared__ float sm[];
    uint32_t smb = (uint32_t)__cvta_generic_to_shared(sm);

    int tid  = threadIdx.x;
    int lane = tid & 31, wid = tid >> 5;
    int g   = lane >> 2;
    int tig = lane & 3;
    int lg  = lane >> 3;          // ldmatrix unit id 0..3
    int lr8 = lane & 7;           // row within unit
    int bh = blockIdx.y;
    int q0 = blockIdx.x * 128;
    const float* Q  = g_q  + (size_t)bh * NN * DH;
    const float* K  = g_k  + (size_t)bh * NN * DH;
    const float* Vt = g_vT + (size_t)bh * DH * NN;

    int lr = tid >> 4;            // 0..15
    int lc = (tid & 15) * 4;      // 0..60

    // ---- Q tile 128x64 + first K/V tiles via cp.async ----
#pragma unroll
    for (int i = 0; i < 8; ++i) {
        int r = lr + i * 16;
        cp16(smb + (FS_QS + r * 68 + lc) * 4, Q + (size_t)(q0 + r) * DH + lc);
    }
#pragma unroll
    for (int i = 0; i < 4; ++i) {
        int r = lr + i * 16;
        cp16(smb + (FS_KS + r * 68 + lc) * 4, K + (size_t)r * DH + lc);
        cp16(smb + (FS_VS + r * 68 + lc) * 4, Vt + (size_t)r * NN + lc);
    }
    CP_COMMIT();

    float oa[8][4] = {};
    float mi[2] = {-INFINITY, -INFINITY};
    float li[2] = {0.f, 0.f};

    const int m_row = wid * 16 + g;
    // ldmatrix lane-address offsets: units {rows+0 c0-3, rows+8 c0-3, rows+0 c4-7, rows+8 c4-7}
    const int frow = (lg & 1) * 8 + lr8;
    const int fcol = (lg >> 1) * 4;
    const uint32_t qa_base = smb + ((uint32_t)(FS_QS + (wid * 16 + frow) * 68 + fcol) << 2);
    const uint32_t pa_base = smb + ((uint32_t)(FS_PS + (wid * 16 + frow) * 68 + fcol) << 2);

    for (int t = 0; t < NT_TILES; ++t) {
        int cur = t & 1;
        int k0 = t * 64;

        // bias prefetch into registers (independent of smem state)
        float2 bb[2][8];
        {
            const float2* bp0 = (const float2*)(g_bias + (size_t)(q0 + m_row) * NN + k0) + tig;
            const float2* bp1 = (const float2*)(g_bias + (size_t)(q0 + m_row + 8) * NN + k0) + tig;
#pragma unroll
            for (int nt = 0; nt < 8; ++nt) {
                bb[0][nt] = bp0[nt * 4];
                bb[1][nt] = bp1[nt * 4];
            }
        }

        if (t > 0) __syncthreads();        // prev PV done reading the buffer we overwrite
        if (t + 1 < NT_TILES) {
            int nxt = cur ^ 1;
#pragma unroll
            for (int i = 0; i < 4; ++i) {
                int r = lr + i * 16;
                cp16(smb + (FS_KS + nxt * FS_STG + r * 68 + lc) * 4,
                     K + (size_t)(k0 + 64 + r) * DH + lc);
                cp16(smb + (FS_VS + nxt * FS_STG + r * 68 + lc) * 4,
                     Vt + (size_t)r * NN + k0 + 64 + lc);
            }
            CP_COMMIT();
            CP_WAIT(1);
        } else {
            CP_WAIT(0);
        }
        __syncthreads();                   // tile t visible

        uint32_t kbase = smb + ((uint32_t)(FS_KS + cur * FS_STG) << 2);
        uint32_t vbase = smb + ((uint32_t)(FS_VS + cur * FS_STG) << 2);
        uint32_t ka[4], va[4];
#pragma unroll
        for (int j = 0; j < 4; ++j) {
            ka[j] = kbase + ((uint32_t)((j * 16 + frow) * 68 + fcol) << 2);
            va[j] = vbase + ((uint32_t)((j * 16 + frow) * 68 + fcol) << 2);
        }

        // ---- S = Q K^T : per ks, 1 A-ldmatrix + 4 B-ldmatrix (2 key-tiles each) ----
        float sa[8][4] = {};
        uint32_t qa = qa_base;
#pragma unroll
        for (int ks = 0; ks < 8; ++ks) {
            uint32_t a0, a1, a2, a3;
            ldsm4(a0, a1, a2, a3, qa);  qa += 32;
#pragma unroll
            for (int j = 0; j < 4; ++j) {
                uint32_t b0, b1, b2, b3;
                ldsm4(b0, b1, b2, b3, ka[j]);  ka[j] += 32;
                MMA_TF32(sa[2 * j],     a0, a1, a2, a3, b0, b2);
                MMA_TF32(sa[2 * j + 1], a0, a1, a2, a3, b1, b3);
            }
        }

        // ---- bias + online softmax (rows m_row, m_row+8) ----
#pragma unroll
        for (int ri = 0; ri < 2; ++ri) {
            float mx = -INFINITY;
#pragma unroll
            for (int nt = 0; nt < 8; ++nt) {
                float v0 = sa[nt][ri * 2 + 0] + bb[ri][nt].x;
                float v1 = sa[nt][ri * 2 + 1] + bb[ri][nt].y;
                sa[nt][ri * 2 + 0] = v0;
                sa[nt][ri * 2 + 1] = v1;
                mx = fmaxf(mx, fmaxf(v0, v1));
            }
            mx = fmaxf(mx, __shfl_xor_sync(0xffffffffu, mx, 1));
            mx = fmaxf(mx, __shfl_xor_sync(0xffffffffu, mx, 2));
            float mnew = fmaxf(mi[ri], mx);
            float f = __expf(mi[ri] - mnew);
            float sum = 0.f;
            float2* psr = (float2*)(sm + FS_PS + (m_row + ri * 8) * 68 + 2 * tig);
#pragma unroll
            for (int nt = 0; nt < 8; ++nt) {
                float e0 = to_tf32(__expf(sa[nt][ri * 2 + 0] - mnew));
                float e1 = to_tf32(__expf(sa[nt][ri * 2 + 1] - mnew));
                sum += e0 + e1;
                psr[nt * 4] = make_float2(e0, e1);
            }
            sum += __shfl_xor_sync(0xffffffffu, sum, 1);
            sum += __shfl_xor_sync(0xffffffffu, sum, 2);
            li[ri] = li[ri] * f + sum;
            mi[ri] = mnew;
#pragma unroll
            for (int nt = 0; nt < 8; ++nt) {
                oa[nt][ri * 2 + 0] *= f;
                oa[nt][ri * 2 + 1] *= f;
            }
        }
        __syncwarp();                      // PS rows are warp-private

        // ---- O += P V : per ks, 1 A-ldmatrix (PS) + 4 B-ldmatrix (VS) ----
        uint32_t pa = pa_base;
#pragma unroll
        for (int ks = 0; ks < 8; ++ks) {
            uint32_t a0, a1, a2, a3;
            ldsm4(a0, a1, a2, a3, pa);  pa += 32;
#pragma unroll
            for (int j = 0; j < 4; ++j) {
                uint32_t b0, b1, b2, b3;
                ldsm4(b0, b1, b2, b3, va[j]);  va[j] += 32;
                MMA_TF32(oa[2 * j],     a0, a1, a2, a3, b0, b2);
                MMA_TF32(oa[2 * j + 1], a0, a1, a2, a3, b1, b3);
            }
        }
    }

    // ---- finalize: write [B, N, H*d] ----
    int b = bh >> 3, h = bh & 7;
    float inv0 = 1.0f / li[0], inv1 = 1.0f / li[1];
#pragma unroll
    for (int nt = 0; nt < 8; ++nt) {
        int col = h * DH + nt * 8 + 2 * tig;
        int r0 = q0 + m_row;
        *(float2*)&g_attn[((size_t)(b * NN + r0)) * HD + col] =
            make_float2(to_tf32(oa[nt][0] * inv0), to_tf32(oa[nt][1] * inv0));
        *(float2*)&g_attn[((size_t)(b * NN + r0 + 8)) * HD + col] =
            make_float2(to_tf32(oa[nt][2] * inv1), to_tf32(oa[nt][3] * inv1));
    }
}

extern "C" void kernel_launch(void* const* d_in, const int* in_sizes, int n_in,
                              void* d_out, int out_size) {
    const float* x     = (const float*)d_in[0];
    const float* gamma = (const float*)d_in[1];
    const float* beta  = (const float*)d_in[2];
    const float* Wqkv  = (const float*)d_in[3];
    const float* Wout  = (const float*)d_in[4];
    const float* bout  = (const float*)d_in[5];
    const float* rel   = (const float*)d_in[6];
    const int*   tmask = (const int*)d_in[7];
    float* out = (float*)d_out;

    round_w_kernel<<<(DD * QKVC / 4 + HD * DD / 4 + 255) / 256, 256>>>(Wqkv, Wout);
    bias_kernel<<<NN * NN / 4 / 256, 256>>>(rel, tmask);
    ln_kernel<<<(BB * NN) / 8, 256>>>(x, gamma, beta);
    qkv_mma_kernel<<<dim3(QKVC / 128, (BB * NN) / 128), 256>>>();

    cudaFuncSetAttribute(flash_mma_kernel, cudaFuncAttributeMaxDynamicSharedMemorySize, FLASH_SMEM);
    flash_mma_kernel<<<dim3(NN / 128, BB * HH), 256, FLASH_SMEM>>>();

    out_mma_kernel<<<dim3(DD / 128, (BB * NN) / 128), 256>>>(bout, out);
}